// round 1
// baseline (speedup 1.0000x reference)
#include <cuda_runtime.h>
#include <cuda_bf16.h>
#include <math.h>

#define LSEQ   4096
#define HIDDEN 4096
#define NH     32
#define NKV    8
#define HD     128
#define CHUNKS 128
#define NC     32
#define QDIM   4096   // NH*HD
#define KVDIM  1024   // NKV*HD

// ---------------- scratch (static device globals; no allocation) ----------------
__device__ float g_q[(size_t)LSEQ * QDIM];
__device__ float g_k[(size_t)LSEQ * KVDIM];
__device__ float g_v[(size_t)LSEQ * KVDIM];
__device__ float g_gate[(size_t)LSEQ * QDIM];
__device__ float g_y[(size_t)LSEQ * QDIM];
__device__ float g_dt[LSEQ * NH];
__device__ float g_G[LSEQ * NH];
__device__ float g_cdec[NC * NH];
__device__ float g_cs[(size_t)NC * NH * HD * HD];
__device__ float g_prev[(size_t)NC * NH * HD * HD];

// ---------------- generic SGEMM: C[M,N] = A[M,K] @ B[N,K]^T ----------------
// 128x128 tile, 256 threads, 8x8 microtile, BK=16. M,N multiples of 128, K of 16.
__global__ void gemm_nt(const float* __restrict__ A, const float* __restrict__ B,
                        float* __restrict__ C, int M, int N, int K) {
    __shared__ float As[16 * 128];
    __shared__ float Bs[16 * 128];
    const int bm = blockIdx.y * 128;
    const int bn = blockIdx.x * 128;
    const int tid = threadIdx.x;
    const int tr = tid >> 4, tc = tid & 15;
    const int row = tid >> 1;
    const int kk0 = (tid & 1) * 8;

    float acc[8][8];
#pragma unroll
    for (int i = 0; i < 8; i++)
#pragma unroll
        for (int j = 0; j < 8; j++) acc[i][j] = 0.f;

    for (int k0 = 0; k0 < K; k0 += 16) {
        const float* ap = A + (size_t)(bm + row) * K + k0 + kk0;
        float4 a0 = *(const float4*)ap;
        float4 a1 = *(const float4*)(ap + 4);
        As[(kk0 + 0) * 128 + row] = a0.x;
        As[(kk0 + 1) * 128 + row] = a0.y;
        As[(kk0 + 2) * 128 + row] = a0.z;
        As[(kk0 + 3) * 128 + row] = a0.w;
        As[(kk0 + 4) * 128 + row] = a1.x;
        As[(kk0 + 5) * 128 + row] = a1.y;
        As[(kk0 + 6) * 128 + row] = a1.z;
        As[(kk0 + 7) * 128 + row] = a1.w;
        const float* bp = B + (size_t)(bn + row) * K + k0 + kk0;
        float4 b0 = *(const float4*)bp;
        float4 b1 = *(const float4*)(bp + 4);
        Bs[(kk0 + 0) * 128 + row] = b0.x;
        Bs[(kk0 + 1) * 128 + row] = b0.y;
        Bs[(kk0 + 2) * 128 + row] = b0.z;
        Bs[(kk0 + 3) * 128 + row] = b0.w;
        Bs[(kk0 + 4) * 128 + row] = b1.x;
        Bs[(kk0 + 5) * 128 + row] = b1.y;
        Bs[(kk0 + 6) * 128 + row] = b1.z;
        Bs[(kk0 + 7) * 128 + row] = b1.w;
        __syncthreads();
#pragma unroll
        for (int kk = 0; kk < 16; kk++) {
            float av[8], bv[8];
#pragma unroll
            for (int i = 0; i < 8; i++) av[i] = As[kk * 128 + tr * 8 + i];
#pragma unroll
            for (int j = 0; j < 8; j++) bv[j] = Bs[kk * 128 + tc * 8 + j];
#pragma unroll
            for (int i = 0; i < 8; i++)
#pragma unroll
                for (int j = 0; j < 8; j++) acc[i][j] += av[i] * bv[j];
        }
        __syncthreads();
    }
#pragma unroll
    for (int i = 0; i < 8; i++) {
        float* cp = C + (size_t)(bm + tr * 8 + i) * N + bn + tc * 8;
        float4 v0 = make_float4(acc[i][0], acc[i][1], acc[i][2], acc[i][3]);
        float4 v1 = make_float4(acc[i][4], acc[i][5], acc[i][6], acc[i][7]);
        *(float4*)cp = v0;
        *(float4*)(cp + 4) = v1;
    }
}

// ---------------- dt = softplus(hs @ Win^T + dt_bias) ----------------
__global__ void dt_kernel(const float* __restrict__ hs, const float* __restrict__ Win,
                          const float* __restrict__ dtb) {
    __shared__ float srow[HIDDEN];
    __shared__ float red[256];
    const int l = blockIdx.x;
    for (int k = threadIdx.x; k < HIDDEN; k += 256) srow[k] = hs[(size_t)l * HIDDEN + k];
    __syncthreads();
    const int h = threadIdx.x & 31;
    const int part = threadIdx.x >> 5;
    const float* w = Win + (size_t)h * HIDDEN + part * 512;
    const float* s = srow + part * 512;
    float acc = 0.f;
#pragma unroll 4
    for (int k = 0; k < 512; k++) acc += s[k] * w[k];
    red[threadIdx.x] = acc;
    __syncthreads();
    if (threadIdx.x < 32) {
        float t = 0.f;
#pragma unroll
        for (int p = 0; p < 8; p++) t += red[p * 32 + h];
        t += dtb[h];
        // softplus, stable
        float sp = fmaxf(t, 0.f) + log1pf(expf(-fabsf(t)));
        g_dt[l * NH + h] = sp;
    }
}

// ---------------- per-(chunk,head) inclusive cumsum of g = dt*A ----------------
__global__ void scan_kernel(const float* __restrict__ A_log) {
    const int hc = blockIdx.x;
    const int h = hc & (NH - 1);
    const int c = hc >> 5;
    const float A = -expf(A_log[h]);
    const int lane = threadIdx.x;
    float carry = 0.f;
    for (int s0 = 0; s0 < CHUNKS; s0 += 32) {
        const int l = c * CHUNKS + s0 + lane;
        float val = g_dt[l * NH + h] * A;
#pragma unroll
        for (int off = 1; off < 32; off <<= 1) {
            float n = __shfl_up_sync(0xffffffffu, val, off);
            if (lane >= off) val += n;
        }
        val += carry;
        g_G[l * NH + h] = val;
        carry = __shfl_sync(0xffffffffu, val, 31);
    }
    if (lane == 31) g_cdec[c * NH + h] = expf(carry);
}

// ---------------- RoPE in place ----------------
__global__ void rope_kernel(float* __restrict__ x, int nheads) {
    const long idx = (long)blockIdx.x * blockDim.x + threadIdx.x;
    const long total = (long)LSEQ * nheads * 64;
    if (idx >= total) return;
    const int d = (int)(idx & 63);
    const int h = (int)((idx >> 6) % nheads);
    const long l = idx / ((long)64 * nheads);
    const float inv = powf(10000.0f, -(2.0f * d) / 128.0f);
    const float ang = (float)l * inv;
    float cs, sn;
    __sincosf(ang, &sn, &cs);
    float* base = x + l * (size_t)(nheads * HD) + (size_t)h * HD;
    const float x1 = base[d];
    const float x2 = base[d + 64];
    base[d]      = x1 * cs - x2 * sn;
    base[d + 64] = x2 * cs + x1 * sn;
}

// ---------------- intra-chunk: scores, decay mask, y_intra, cstates ----------------
// grid (NC, NH), 256 threads, dynamic smem = (128*129 + 2*16*128) floats
__global__ void intra_kernel() {
    extern __shared__ float smem[];
    float* sP = smem;                 // 128*129, P^T (stored [j][i])
    float* sA = sP + 128 * 129;       // 16*128
    float* sB = sA + 16 * 128;        // 16*128
    __shared__ float sG[128];
    __shared__ float sDt[128];

    const int c = blockIdx.x, h = blockIdx.y;
    const int kvh = h >> 2;
    const int tid = threadIdx.x;
    const int tr = tid >> 4, tc = tid & 15;
    const float* qp = g_q + (size_t)(c * CHUNKS) * QDIM + (size_t)h * HD;
    const float* kp = g_k + (size_t)(c * CHUNKS) * KVDIM + (size_t)kvh * HD;
    const float* vp = g_v + (size_t)(c * CHUNKS) * KVDIM + (size_t)kvh * HD;

    if (tid < 128) {
        sG[tid] = g_G[(c * CHUNKS + tid) * NH + h];
        sDt[tid] = g_dt[(c * CHUNKS + tid) * NH + h];
    }
    __syncthreads();
    const float Glast = sG[127];

    float acc[8][8];
#pragma unroll
    for (int i = 0; i < 8; i++)
#pragma unroll
        for (int j = 0; j < 8; j++) acc[i][j] = 0.f;

    // Phase 1: S = Q @ K^T   (K-dim = head dim, 128, BK=16)
    const int rowA = tid >> 1;
    const int kk0 = (tid & 1) * 8;
    for (int d0 = 0; d0 < HD; d0 += 16) {
        const float* ap = qp + (size_t)rowA * QDIM + d0 + kk0;
        float4 a0 = *(const float4*)ap;
        float4 a1 = *(const float4*)(ap + 4);
        sA[(kk0 + 0) * 128 + rowA] = a0.x;
        sA[(kk0 + 1) * 128 + rowA] = a0.y;
        sA[(kk0 + 2) * 128 + rowA] = a0.z;
        sA[(kk0 + 3) * 128 + rowA] = a0.w;
        sA[(kk0 + 4) * 128 + rowA] = a1.x;
        sA[(kk0 + 5) * 128 + rowA] = a1.y;
        sA[(kk0 + 6) * 128 + rowA] = a1.z;
        sA[(kk0 + 7) * 128 + rowA] = a1.w;
        const float* bp = kp + (size_t)rowA * KVDIM + d0 + kk0;
        float4 b0 = *(const float4*)bp;
        float4 b1 = *(const float4*)(bp + 4);
        sB[(kk0 + 0) * 128 + rowA] = b0.x;
        sB[(kk0 + 1) * 128 + rowA] = b0.y;
        sB[(kk0 + 2) * 128 + rowA] = b0.z;
        sB[(kk0 + 3) * 128 + rowA] = b0.w;
        sB[(kk0 + 4) * 128 + rowA] = b1.x;
        sB[(kk0 + 5) * 128 + rowA] = b1.y;
        sB[(kk0 + 6) * 128 + rowA] = b1.z;
        sB[(kk0 + 7) * 128 + rowA] = b1.w;
        __syncthreads();
#pragma unroll
        for (int kk = 0; kk < 16; kk++) {
            float av[8], bv[8];
#pragma unroll
            for (int i = 0; i < 8; i++) av[i] = sA[kk * 128 + tr * 8 + i];
#pragma unroll
            for (int j = 0; j < 8; j++) bv[j] = sB[kk * 128 + tc * 8 + j];
#pragma unroll
            for (int i = 0; i < 8; i++)
#pragma unroll
                for (int j = 0; j < 8; j++) acc[i][j] += av[i] * bv[j];
        }
        __syncthreads();
    }

    // Phase 2: causal decay mask -> sP[j][i] (transposed, pitch 129)
#pragma unroll
    for (int ii = 0; ii < 8; ii++) {
        const int i = tr * 8 + ii;
        const float Gi = sG[i];
#pragma unroll
        for (int jj = 0; jj < 8; jj++) {
            const int j = tc * 8 + jj;
            const float p = (i >= j) ? acc[ii][jj] * expf(Gi - sG[j]) : 0.f;
            sP[j * 129 + i] = p;
        }
    }
    __syncthreads();

    // Phase 3: y_intra = P @ X   (X[j][e] = v[j][e]*dt[j]); K-dim = j
#pragma unroll
    for (int i = 0; i < 8; i++)
#pragma unroll
        for (int j = 0; j < 8; j++) acc[i][j] = 0.f;
    {
        const int kkl = tid >> 4;           // 0..15 (slice row)
        const int e0 = (tid & 15) * 8;      // 0..120
        for (int j0 = 0; j0 < 128; j0 += 16) {
            const float dtv = sDt[j0 + kkl];
            const float* xp = vp + (size_t)(j0 + kkl) * KVDIM + e0;
            float4 x0 = *(const float4*)xp;
            float4 x1 = *(const float4*)(xp + 4);
            sB[kkl * 128 + e0 + 0] = x0.x * dtv;
            sB[kkl * 128 + e0 + 1] = x0.y * dtv;
            sB[kkl * 128 + e0 + 2] = x0.z * dtv;
            sB[kkl * 128 + e0 + 3] = x0.w * dtv;
            sB[kkl * 128 + e0 + 4] = x1.x * dtv;
            sB[kkl * 128 + e0 + 5] = x1.y * dtv;
            sB[kkl * 128 + e0 + 6] = x1.z * dtv;
            sB[kkl * 128 + e0 + 7] = x1.w * dtv;
            __syncthreads();
#pragma unroll
            for (int kk = 0; kk < 16; kk++) {
                float av[8], bv[8];
#pragma unroll
                for (int i = 0; i < 8; i++) av[i] = sP[(j0 + kk) * 129 + tr * 8 + i];
#pragma unroll
                for (int j = 0; j < 8; j++) bv[j] = sB[kk * 128 + tc * 8 + j];
#pragma unroll
                for (int i = 0; i < 8; i++)
#pragma unroll
                    for (int j = 0; j < 8; j++) acc[i][j] += av[i] * bv[j];
            }
            __syncthreads();
        }
    }
#pragma unroll
    for (int ii = 0; ii < 8; ii++) {
        float* yp = g_y + (size_t)(c * CHUNKS + tr * 8 + ii) * QDIM + (size_t)h * HD + tc * 8;
        *(float4*)yp = make_float4(acc[ii][0], acc[ii][1], acc[ii][2], acc[ii][3]);
        *(float4*)(yp + 4) = make_float4(acc[ii][4], acc[ii][5], acc[ii][6], acc[ii][7]);
    }

    // Phase 4: cstates[d][e] = sum_j k[j][d]*exp(Glast-G_j) * x[j][e]
#pragma unroll
    for (int i = 0; i < 8; i++)
#pragma unroll
        for (int j = 0; j < 8; j++) acc[i][j] = 0.f;
    {
        const int kkl = tid >> 4;
        const int e0 = (tid & 15) * 8;
        for (int j0 = 0; j0 < 128; j0 += 16) {
            const float w = expf(Glast - sG[j0 + kkl]);
            const float dtv = sDt[j0 + kkl];
            const float* kp2 = kp + (size_t)(j0 + kkl) * KVDIM + e0;
            const float* xp = vp + (size_t)(j0 + kkl) * KVDIM + e0;
            float4 k0v = *(const float4*)kp2;
            float4 k1v = *(const float4*)(kp2 + 4);
            float4 x0 = *(const float4*)xp;
            float4 x1 = *(const float4*)(xp + 4);
            sA[kkl * 128 + e0 + 0] = k0v.x * w;
            sA[kkl * 128 + e0 + 1] = k0v.y * w;
            sA[kkl * 128 + e0 + 2] = k0v.z * w;
            sA[kkl * 128 + e0 + 3] = k0v.w * w;
            sA[kkl * 128 + e0 + 4] = k1v.x * w;
            sA[kkl * 128 + e0 + 5] = k1v.y * w;
            sA[kkl * 128 + e0 + 6] = k1v.z * w;
            sA[kkl * 128 + e0 + 7] = k1v.w * w;
            sB[kkl * 128 + e0 + 0] = x0.x * dtv;
            sB[kkl * 128 + e0 + 1] = x0.y * dtv;
            sB[kkl * 128 + e0 + 2] = x0.z * dtv;
            sB[kkl * 128 + e0 + 3] = x0.w * dtv;
            sB[kkl * 128 + e0 + 4] = x1.x * dtv;
            sB[kkl * 128 + e0 + 5] = x1.y * dtv;
            sB[kkl * 128 + e0 + 6] = x1.z * dtv;
            sB[kkl * 128 + e0 + 7] = x1.w * dtv;
            __syncthreads();
#pragma unroll
            for (int kk = 0; kk < 16; kk++) {
                float av[8], bv[8];
#pragma unroll
                for (int i = 0; i < 8; i++) av[i] = sA[kk * 128 + tr * 8 + i];
#pragma unroll
                for (int j = 0; j < 8; j++) bv[j] = sB[kk * 128 + tc * 8 + j];
#pragma unroll
                for (int i = 0; i < 8; i++)
#pragma unroll
                    for (int j = 0; j < 8; j++) acc[i][j] += av[i] * bv[j];
            }
            __syncthreads();
        }
    }
    float* csp = g_cs + (size_t)(c * NH + h) * HD * HD;
#pragma unroll
    for (int ii = 0; ii < 8; ii++) {
        float* cp = csp + (size_t)(tr * 8 + ii) * HD + tc * 8;
        *(float4*)cp = make_float4(acc[ii][0], acc[ii][1], acc[ii][2], acc[ii][3]);
        *(float4*)(cp + 4) = make_float4(acc[ii][4], acc[ii][5], acc[ii][6], acc[ii][7]);
    }
}

// ---------------- sequential chunk recurrence ----------------
__global__ void recur_kernel() {
    const int idx = blockIdx.x * blockDim.x + threadIdx.x;  // over NH*HD*HD
    if (idx >= NH * HD * HD) return;
    const int h = idx / (HD * HD);
    const int de = idx % (HD * HD);
    float state = 0.f;
#pragma unroll 1
    for (int c = 0; c < NC; c++) {
        const size_t off = (size_t)(c * NH + h) * HD * HD + de;
        g_prev[off] = state;
        state = state * g_cdec[c * NH + h] + g_cs[off];
    }
}

// ---------------- inter-chunk + combine + RMSNorm + SiLU gate ----------------
__global__ void inter_kernel(const float* __restrict__ gnorm) {
    extern __shared__ float smem[];
    float* sY = smem;               // 128*129
    float* sA = sY + 128 * 129;     // 16*128
    float* sB = sA + 16 * 128;      // 16*128
    __shared__ float sG[128];
    __shared__ float sScale[128];
    __shared__ float sGn[128];

    const int c = blockIdx.x, h = blockIdx.y;
    const int tid = threadIdx.x;
    const int tr = tid >> 4, tc = tid & 15;
    const float* qp = g_q + (size_t)(c * CHUNKS) * QDIM + (size_t)h * HD;
    const float* pp = g_prev + (size_t)(c * NH + h) * HD * HD;

    if (tid < 128) {
        sG[tid] = g_G[(c * CHUNKS + tid) * NH + h];
        sGn[tid] = gnorm[tid];
    }
    __syncthreads();

    float acc[8][8];
#pragma unroll
    for (int i = 0; i < 8; i++)
#pragma unroll
        for (int j = 0; j < 8; j++) acc[i][j] = 0.f;

    const int rowA = tid >> 1;
    const int kk0 = (tid & 1) * 8;
    const int kkl = tid >> 4;
    const int e0 = (tid & 15) * 8;
    for (int d0 = 0; d0 < HD; d0 += 16) {
        const float eg = expf(sG[rowA]);
        const float* ap = qp + (size_t)rowA * QDIM + d0 + kk0;
        float4 a0 = *(const float4*)ap;
        float4 a1 = *(const float4*)(ap + 4);
        sA[(kk0 + 0) * 128 + rowA] = a0.x * eg;
        sA[(kk0 + 1) * 128 + rowA] = a0.y * eg;
        sA[(kk0 + 2) * 128 + rowA] = a0.z * eg;
        sA[(kk0 + 3) * 128 + rowA] = a0.w * eg;
        sA[(kk0 + 4) * 128 + rowA] = a1.x * eg;
        sA[(kk0 + 5) * 128 + rowA] = a1.y * eg;
        sA[(kk0 + 6) * 128 + rowA] = a1.z * eg;
        sA[(kk0 + 7) * 128 + rowA] = a1.w * eg;
        const float* bp = pp + (size_t)(d0 + kkl) * HD + e0;
        float4 b0 = *(const float4*)bp;
        float4 b1 = *(const float4*)(bp + 4);
        sB[kkl * 128 + e0 + 0] = b0.x;
        sB[kkl * 128 + e0 + 1] = b0.y;
        sB[kkl * 128 + e0 + 2] = b0.z;
        sB[kkl * 128 + e0 + 3] = b0.w;
        sB[kkl * 128 + e0 + 4] = b1.x;
        sB[kkl * 128 + e0 + 5] = b1.y;
        sB[kkl * 128 + e0 + 6] = b1.z;
        sB[kkl * 128 + e0 + 7] = b1.w;
        __syncthreads();
#pragma unroll
        for (int kk = 0; kk < 16; kk++) {
            float av[8], bv[8];
#pragma unroll
            for (int i = 0; i < 8; i++) av[i] = sA[kk * 128 + tr * 8 + i];
#pragma unroll
            for (int j = 0; j < 8; j++) bv[j] = sB[kk * 128 + tc * 8 + j];
#pragma unroll
            for (int i = 0; i < 8; i++)
#pragma unroll
                for (int j = 0; j < 8; j++) acc[i][j] += av[i] * bv[j];
        }
        __syncthreads();
    }

    // combine with intra, stage into sY[i][e]
#pragma unroll
    for (int ii = 0; ii < 8; ii++) {
        const int i = tr * 8 + ii;
        const float* yin = g_y + (size_t)(c * CHUNKS + i) * QDIM + (size_t)h * HD + tc * 8;
#pragma unroll
        for (int jj = 0; jj < 8; jj++) {
            sY[i * 129 + tc * 8 + jj] = acc[ii][jj] + yin[jj];
        }
    }
    __syncthreads();

    // RMS per row
    if (tid < 128) {
        float s = 0.f;
#pragma unroll 4
        for (int e = 0; e < 128; e++) {
            float t = sY[tid * 129 + e];
            s += t * t;
        }
        sScale[tid] = rsqrtf(s * (1.0f / 128.0f) + 1e-5f);
    }
    __syncthreads();

    // gate + write
    for (int idx = tid; idx < 128 * 128; idx += 256) {
        const int i = idx >> 7, e = idx & 127;
        const size_t off = (size_t)(c * CHUNKS + i) * QDIM + (size_t)h * HD + e;
        const float gv = g_gate[off];
        const float sig = 1.f / (1.f + expf(-gv));
        g_y[off] = sY[i * 129 + e] * sScale[i] * sGn[e] * gv * sig;
    }
}

// ---------------- launch ----------------
extern "C" void kernel_launch(void* const* d_in, const int* in_sizes, int n_in,
                              void* d_out, int out_size) {
    const float* hs      = (const float*)d_in[0];
    const float* Wq      = (const float*)d_in[1];
    const float* Wk      = (const float*)d_in[2];
    const float* Wv      = (const float*)d_in[3];
    const float* Wo      = (const float*)d_in[4];
    const float* Wg      = (const float*)d_in[5];
    const float* Win     = (const float*)d_in[6];
    const float* dt_bias = (const float*)d_in[7];
    const float* A_log   = (const float*)d_in[8];
    const float* gnorm   = (const float*)d_in[9];
    float* out = (float*)d_out;

    float *q, *k, *v, *gate, *y;
    cudaGetSymbolAddress((void**)&q, g_q);
    cudaGetSymbolAddress((void**)&k, g_k);
    cudaGetSymbolAddress((void**)&v, g_v);
    cudaGetSymbolAddress((void**)&gate, g_gate);
    cudaGetSymbolAddress((void**)&y, g_y);

    const int SMEM_BIG = (128 * 129 + 2 * 16 * 128) * (int)sizeof(float);
    cudaFuncSetAttribute(intra_kernel, cudaFuncAttributeMaxDynamicSharedMemorySize, SMEM_BIG);
    cudaFuncSetAttribute(inter_kernel, cudaFuncAttributeMaxDynamicSharedMemorySize, SMEM_BIG);

    // projections
    gemm_nt<<<dim3(QDIM / 128, LSEQ / 128), 256>>>(hs, Wq, q, LSEQ, QDIM, HIDDEN);
    gemm_nt<<<dim3(KVDIM / 128, LSEQ / 128), 256>>>(hs, Wk, k, LSEQ, KVDIM, HIDDEN);
    gemm_nt<<<dim3(KVDIM / 128, LSEQ / 128), 256>>>(hs, Wv, v, LSEQ, KVDIM, HIDDEN);
    gemm_nt<<<dim3(QDIM / 128, LSEQ / 128), 256>>>(hs, Wg, gate, LSEQ, QDIM, HIDDEN);
    dt_kernel<<<LSEQ, 256>>>(hs, Win, dt_bias);
    scan_kernel<<<NC * NH, 32>>>(A_log);

    // rope
    {
        long tq = (long)LSEQ * NH * 64;
        rope_kernel<<<(unsigned)((tq + 255) / 256), 256>>>(q, NH);
        long tk = (long)LSEQ * NKV * 64;
        rope_kernel<<<(unsigned)((tk + 255) / 256), 256>>>(k, NKV);
    }

    // attention
    intra_kernel<<<dim3(NC, NH), 256, SMEM_BIG>>>();
    recur_kernel<<<(NH * HD * HD + 1023) / 1024, 1024>>>();
    inter_kernel<<<dim3(NC, NH), 256, SMEM_BIG>>>(gnorm);

    // output projection
    gemm_nt<<<dim3(HIDDEN / 128, LSEQ / 128), 256>>>(y, Wo, out, LSEQ, HIDDEN, QDIM);
}

// round 3
// speedup vs baseline: 2.1681x; 2.1681x over previous
#include <cuda_runtime.h>
#include <cuda_bf16.h>
#include <math.h>

#define LSEQ   4096
#define HIDDEN 4096
#define NH     32
#define NKV    8
#define HD     128
#define CHUNKS 128
#define NC     32
#define QDIM   4096   // NH*HD
#define KVDIM  1024   // NKV*HD

// ---------------- scratch (static device globals; no allocation) ----------------
__device__ float g_q[(size_t)LSEQ * QDIM];
__device__ float g_k[(size_t)LSEQ * KVDIM];
__device__ float g_v[(size_t)LSEQ * KVDIM];
__device__ float g_gate[(size_t)LSEQ * QDIM];
__device__ float g_y[(size_t)LSEQ * QDIM];
__device__ float g_dt[LSEQ * NH];
__device__ float g_G[LSEQ * NH];
__device__ float g_cdec[NC * NH];
__device__ float g_cs[(size_t)NC * NH * HD * HD];
__device__ float g_prev[(size_t)NC * NH * HD * HD];

__device__ __forceinline__ unsigned pack_bf2(float a, float b) {
    __nv_bfloat162 t = __floats2bfloat162_rn(a, b);
    return reinterpret_cast<unsigned&>(t);
}

// ---------------- bf16x3 tensor-core GEMM: C[M,N] = A[M,K] @ B[N,K]^T ----------------
// Error-compensated split: x = hi + lo (bf16 each); product = hh + hl + lh (fp32 acc).
// 128x128 CTA tile, BK=32, 256 threads (8 warps 2x4), warp tile 64x32, m16n8k16 MMA.
// smem fragment-permuted: A frag = 1 LDS.128, B frag = 1 LDS.64. M,N%128==0, K%32==0.
__global__ void __launch_bounds__(256, 1) gemm_bf16x3(const float* __restrict__ A,
                                                      const float* __restrict__ B,
                                                      float* __restrict__ C,
                                                      int M, int N, int K) {
    extern __shared__ unsigned smem_u[];
    // per buffer (8192 u32): A_hi @0, A_lo @2048, B_hi @4096, B_lo @6144
    const int tid = threadIdx.x;
    const int warp = tid >> 5, lane = tid & 31;
    const int wm = warp >> 2, wn = warp & 3;   // 2 x 4 warp grid
    const int bm = blockIdx.y * 128, bn = blockIdx.x * 128;

    float acc[4][4][4];
#pragma unroll
    for (int a = 0; a < 4; a++)
#pragma unroll
        for (int b = 0; b < 4; b++)
#pragma unroll
            for (int c = 0; c < 4; c++) acc[a][b][c] = 0.f;

    // staging: 4 float4 loads per matrix per thread
    const float* a_g[4];
    const float* b_g[4];
    int a_st[4], b_st[4];
#pragma unroll
    for (int i = 0; i < 4; i++) {
        const int idx = tid + i * 256;
        const int row = idx >> 3, c4 = idx & 7;
        const int k0 = c4 * 4;
        const int ks = k0 >> 4, ki = k0 & 15;
        a_g[i] = A + (size_t)(bm + row) * K + k0;
        b_g[i] = B + (size_t)(bn + row) * K + k0;
        // A: fragment (m16n8k16 row): lane=(ri&7)*4+((ki&7)>>1), reg=(ri>>3)+((ki>>3)<<1)
        const int ri = row & 15, tm = row >> 4;
        const int laneA = (ri & 7) * 4 + ((ki & 7) >> 1);
        const int regA = (ri >> 3) + ((ki >> 3) << 1);
        a_st[i] = ((ks * 8 + tm) * 32 + laneA) * 4 + regA;
        // B: fragment (col): lane=ci*4+((ki&7)>>1), reg=ki>>3
        const int ci = row & 7, tn = row >> 3;
        const int laneB = ci * 4 + ((ki & 7) >> 1);
        const int regB = ki >> 3;
        b_st[i] = ((ks * 16 + tn) * 32 + laneB) * 2 + regB;
    }

    float4 ar[4], br[4];
#pragma unroll
    for (int i = 0; i < 4; i++) {
        ar[i] = *(const float4*)(a_g[i]);
        br[i] = *(const float4*)(b_g[i]);
    }

    // store tiles into buffer buf
    auto store_tiles = [&](unsigned* base) {
        unsigned* Ah = base;
        unsigned* Al = base + 2048;
        unsigned* Bh = base + 4096;
        unsigned* Bl = base + 6144;
#pragma unroll
        for (int i = 0; i < 4; i++) {
            // A
            {
                float4 v = ar[i];
                __nv_bfloat162 h01 = __floats2bfloat162_rn(v.x, v.y);
                __nv_bfloat162 h23 = __floats2bfloat162_rn(v.z, v.w);
                float2 f01 = __bfloat1622float2(h01);
                float2 f23 = __bfloat1622float2(h23);
                Ah[a_st[i]]     = reinterpret_cast<unsigned&>(h01);
                Ah[a_st[i] + 4] = reinterpret_cast<unsigned&>(h23);
                Al[a_st[i]]     = pack_bf2(v.x - f01.x, v.y - f01.y);
                Al[a_st[i] + 4] = pack_bf2(v.z - f23.x, v.w - f23.y);
            }
            // B
            {
                float4 v = br[i];
                __nv_bfloat162 h01 = __floats2bfloat162_rn(v.x, v.y);
                __nv_bfloat162 h23 = __floats2bfloat162_rn(v.z, v.w);
                float2 f01 = __bfloat1622float2(h01);
                float2 f23 = __bfloat1622float2(h23);
                Bh[b_st[i]]     = reinterpret_cast<unsigned&>(h01);
                Bh[b_st[i] + 2] = reinterpret_cast<unsigned&>(h23);
                Bl[b_st[i]]     = pack_bf2(v.x - f01.x, v.y - f01.y);
                Bl[b_st[i] + 2] = pack_bf2(v.z - f23.x, v.w - f23.y);
            }
        }
    };

    store_tiles(smem_u);
    __syncthreads();

    const int nk = K >> 5;
    for (int kb = 0; kb < nk; kb++) {
        const int cur = kb & 1;
        const bool has_next = (kb + 1) < nk;
        if (has_next) {
            const int off = (kb + 1) * 32;
#pragma unroll
            for (int i = 0; i < 4; i++) {
                ar[i] = *(const float4*)(a_g[i] + off);
                br[i] = *(const float4*)(b_g[i] + off);
            }
        }
        const unsigned* base = smem_u + cur * 8192;
        const unsigned* Ah = base;
        const unsigned* Al = base + 2048;
        const unsigned* Bh = base + 4096;
        const unsigned* Bl = base + 6144;
#pragma unroll
        for (int ks = 0; ks < 2; ks++) {
            unsigned bh[4][2], bl[4][2];
#pragma unroll
            for (int nt = 0; nt < 4; nt++) {
                const int tn = wn * 4 + nt;
                uint2 vh = *(const uint2*)(Bh + ((ks * 16 + tn) * 32 + lane) * 2);
                uint2 vl = *(const uint2*)(Bl + ((ks * 16 + tn) * 32 + lane) * 2);
                bh[nt][0] = vh.x; bh[nt][1] = vh.y;
                bl[nt][0] = vl.x; bl[nt][1] = vl.y;
            }
#pragma unroll
            for (int mt = 0; mt < 4; mt++) {
                const int tm = wm * 4 + mt;
                uint4 avh = *(const uint4*)(Ah + ((ks * 8 + tm) * 32 + lane) * 4);
                uint4 avl = *(const uint4*)(Al + ((ks * 8 + tm) * 32 + lane) * 4);
#pragma unroll
                for (int nt = 0; nt < 4; nt++) {
                    asm volatile(
                        "mma.sync.aligned.m16n8k16.row.col.f32.bf16.bf16.f32 "
                        "{%0,%1,%2,%3}, {%4,%5,%6,%7}, {%8,%9}, {%0,%1,%2,%3};"
                        : "+f"(acc[mt][nt][0]), "+f"(acc[mt][nt][1]),
                          "+f"(acc[mt][nt][2]), "+f"(acc[mt][nt][3])
                        : "r"(avh.x), "r"(avh.y), "r"(avh.z), "r"(avh.w),
                          "r"(bh[nt][0]), "r"(bh[nt][1]));
                    asm volatile(
                        "mma.sync.aligned.m16n8k16.row.col.f32.bf16.bf16.f32 "
                        "{%0,%1,%2,%3}, {%4,%5,%6,%7}, {%8,%9}, {%0,%1,%2,%3};"
                        : "+f"(acc[mt][nt][0]), "+f"(acc[mt][nt][1]),
                          "+f"(acc[mt][nt][2]), "+f"(acc[mt][nt][3])
                        : "r"(avh.x), "r"(avh.y), "r"(avh.z), "r"(avh.w),
                          "r"(bl[nt][0]), "r"(bl[nt][1]));
                    asm volatile(
                        "mma.sync.aligned.m16n8k16.row.col.f32.bf16.bf16.f32 "
                        "{%0,%1,%2,%3}, {%4,%5,%6,%7}, {%8,%9}, {%0,%1,%2,%3};"
                        : "+f"(acc[mt][nt][0]), "+f"(acc[mt][nt][1]),
                          "+f"(acc[mt][nt][2]), "+f"(acc[mt][nt][3])
                        : "r"(avl.x), "r"(avl.y), "r"(avl.z), "r"(avl.w),
                          "r"(bh[nt][0]), "r"(bh[nt][1]));
                }
            }
        }
        if (has_next) {
            store_tiles(smem_u + ((kb + 1) & 1) * 8192);
            __syncthreads();
        }
    }

    // epilogue
#pragma unroll
    for (int mt = 0; mt < 4; mt++) {
        const int row0 = bm + wm * 64 + mt * 16 + (lane >> 2);
#pragma unroll
        for (int nt = 0; nt < 4; nt++) {
            const int col = bn + wn * 32 + nt * 8 + (lane & 3) * 2;
            *(float2*)(C + (size_t)row0 * N + col) = make_float2(acc[mt][nt][0], acc[mt][nt][1]);
            *(float2*)(C + (size_t)(row0 + 8) * N + col) = make_float2(acc[mt][nt][2], acc[mt][nt][3]);
        }
    }
}

// ---------------- dt = softplus(hs @ Win^T + dt_bias) ----------------
__global__ void dt_kernel(const float* __restrict__ hs, const float* __restrict__ Win,
                          const float* __restrict__ dtb) {
    __shared__ float srow[HIDDEN];
    __shared__ float red[256];
    const int l = blockIdx.x;
    for (int k = threadIdx.x; k < HIDDEN; k += 256) srow[k] = hs[(size_t)l * HIDDEN + k];
    __syncthreads();
    const int h = threadIdx.x & 31;
    const int part = threadIdx.x >> 5;
    const float* w = Win + (size_t)h * HIDDEN + part * 512;
    const float* s = srow + part * 512;
    float acc = 0.f;
#pragma unroll 4
    for (int k = 0; k < 512; k++) acc += s[k] * w[k];
    red[threadIdx.x] = acc;
    __syncthreads();
    if (threadIdx.x < 32) {
        float t = 0.f;
#pragma unroll
        for (int p = 0; p < 8; p++) t += red[p * 32 + h];
        t += dtb[h];
        float sp = fmaxf(t, 0.f) + log1pf(expf(-fabsf(t)));
        g_dt[l * NH + h] = sp;
    }
}

// ---------------- per-(chunk,head) inclusive cumsum of g = dt*A ----------------
__global__ void scan_kernel(const float* __restrict__ A_log) {
    const int hc = blockIdx.x;
    const int h = hc & (NH - 1);
    const int c = hc >> 5;
    const float A = -expf(A_log[h]);
    const int lane = threadIdx.x;
    float carry = 0.f;
    for (int s0 = 0; s0 < CHUNKS; s0 += 32) {
        const int l = c * CHUNKS + s0 + lane;
        float val = g_dt[l * NH + h] * A;
#pragma unroll
        for (int off = 1; off < 32; off <<= 1) {
            float n = __shfl_up_sync(0xffffffffu, val, off);
            if (lane >= off) val += n;
        }
        val += carry;
        g_G[l * NH + h] = val;
        carry = __shfl_sync(0xffffffffu, val, 31);
    }
    if (lane == 31) g_cdec[c * NH + h] = expf(carry);
}

// ---------------- RoPE in place ----------------
__global__ void rope_kernel(float* __restrict__ x, int nheads) {
    const long idx = (long)blockIdx.x * blockDim.x + threadIdx.x;
    const long total = (long)LSEQ * nheads * 64;
    if (idx >= total) return;
    const int d = (int)(idx & 63);
    const int h = (int)((idx >> 6) % nheads);
    const long l = idx / ((long)64 * nheads);
    const float inv = powf(10000.0f, -(2.0f * d) / 128.0f);
    const float ang = (float)l * inv;
    float cs, sn;
    __sincosf(ang, &sn, &cs);
    float* base = x + l * (size_t)(nheads * HD) + (size_t)h * HD;
    const float x1 = base[d];
    const float x2 = base[d + 64];
    base[d]      = x1 * cs - x2 * sn;
    base[d + 64] = x2 * cs + x1 * sn;
}

// ---------------- intra-chunk: scores, decay mask, y_intra, cstates ----------------
__global__ void intra_kernel() {
    extern __shared__ float smem[];
    float* sP = smem;                 // 128*129, P^T (stored [j][i])
    float* sA = sP + 128 * 129;       // 16*128
    float* sB = sA + 16 * 128;        // 16*128
    __shared__ float sG[128];
    __shared__ float sDt[128];

    const int c = blockIdx.x, h = blockIdx.y;
    const int kvh = h >> 2;
    const int tid = threadIdx.x;
    const int tr = tid >> 4, tc = tid & 15;
    const float* qp = g_q + (size_t)(c * CHUNKS) * QDIM + (size_t)h * HD;
    const float* kp = g_k + (size_t)(c * CHUNKS) * KVDIM + (size_t)kvh * HD;
    const float* vp = g_v + (size_t)(c * CHUNKS) * KVDIM + (size_t)kvh * HD;

    if (tid < 128) {
        sG[tid] = g_G[(c * CHUNKS + tid) * NH + h];
        sDt[tid] = g_dt[(c * CHUNKS + tid) * NH + h];
    }
    __syncthreads();
    const float Glast = sG[127];

    float acc[8][8];
#pragma unroll
    for (int i = 0; i < 8; i++)
#pragma unroll
        for (int j = 0; j < 8; j++) acc[i][j] = 0.f;

    const int rowA = tid >> 1;
    const int kk0 = (tid & 1) * 8;
    for (int d0 = 0; d0 < HD; d0 += 16) {
        const float* ap = qp + (size_t)rowA * QDIM + d0 + kk0;
        float4 a0 = *(const float4*)ap;
        float4 a1 = *(const float4*)(ap + 4);
        sA[(kk0 + 0) * 128 + rowA] = a0.x;
        sA[(kk0 + 1) * 128 + rowA] = a0.y;
        sA[(kk0 + 2) * 128 + rowA] = a0.z;
        sA[(kk0 + 3) * 128 + rowA] = a0.w;
        sA[(kk0 + 4) * 128 + rowA] = a1.x;
        sA[(kk0 + 5) * 128 + rowA] = a1.y;
        sA[(kk0 + 6) * 128 + rowA] = a1.z;
        sA[(kk0 + 7) * 128 + rowA] = a1.w;
        const float* bp = kp + (size_t)rowA * KVDIM + d0 + kk0;
        float4 b0 = *(const float4*)bp;
        float4 b1 = *(const float4*)(bp + 4);
        sB[(kk0 + 0) * 128 + rowA] = b0.x;
        sB[(kk0 + 1) * 128 + rowA] = b0.y;
        sB[(kk0 + 2) * 128 + rowA] = b0.z;
        sB[(kk0 + 3) * 128 + rowA] = b0.w;
        sB[(kk0 + 4) * 128 + rowA] = b1.x;
        sB[(kk0 + 5) * 128 + rowA] = b1.y;
        sB[(kk0 + 6) * 128 + rowA] = b1.z;
        sB[(kk0 + 7) * 128 + rowA] = b1.w;
        __syncthreads();
#pragma unroll
        for (int kk = 0; kk < 16; kk++) {
            float av[8], bv[8];
#pragma unroll
            for (int i = 0; i < 8; i++) av[i] = sA[kk * 128 + tr * 8 + i];
#pragma unroll
            for (int j = 0; j < 8; j++) bv[j] = sB[kk * 128 + tc * 8 + j];
#pragma unroll
            for (int i = 0; i < 8; i++)
#pragma unroll
                for (int j = 0; j < 8; j++) acc[i][j] += av[i] * bv[j];
        }
        __syncthreads();
    }

#pragma unroll
    for (int ii = 0; ii < 8; ii++) {
        const int i = tr * 8 + ii;
        const float Gi = sG[i];
#pragma unroll
        for (int jj = 0; jj < 8; jj++) {
            const int j = tc * 8 + jj;
            const float p = (i >= j) ? acc[ii][jj] * expf(Gi - sG[j]) : 0.f;
            sP[j * 129 + i] = p;
        }
    }
    __syncthreads();

#pragma unroll
    for (int i = 0; i < 8; i++)
#pragma unroll
        for (int j = 0; j < 8; j++) acc[i][j] = 0.f;
    {
        const int kkl = tid >> 4;
        const int e0 = (tid & 15) * 8;
        for (int j0 = 0; j0 < 128; j0 += 16) {
            const float dtv = sDt[j0 + kkl];
            const float* xp = vp + (size_t)(j0 + kkl) * KVDIM + e0;
            float4 x0 = *(const float4*)xp;
            float4 x1 = *(const float4*)(xp + 4);
            sB[kkl * 128 + e0 + 0] = x0.x * dtv;
            sB[kkl * 128 + e0 + 1] = x0.y * dtv;
            sB[kkl * 128 + e0 + 2] = x0.z * dtv;
            sB[kkl * 128 + e0 + 3] = x0.w * dtv;
            sB[kkl * 128 + e0 + 4] = x1.x * dtv;
            sB[kkl * 128 + e0 + 5] = x1.y * dtv;
            sB[kkl * 128 + e0 + 6] = x1.z * dtv;
            sB[kkl * 128 + e0 + 7] = x1.w * dtv;
            __syncthreads();
#pragma unroll
            for (int kk = 0; kk < 16; kk++) {
                float av[8], bv[8];
#pragma unroll
                for (int i = 0; i < 8; i++) av[i] = sP[(j0 + kk) * 129 + tr * 8 + i];
#pragma unroll
                for (int j = 0; j < 8; j++) bv[j] = sB[kk * 128 + tc * 8 + j];
#pragma unroll
                for (int i = 0; i < 8; i++)
#pragma unroll
                    for (int j = 0; j < 8; j++) acc[i][j] += av[i] * bv[j];
            }
            __syncthreads();
        }
    }
#pragma unroll
    for (int ii = 0; ii < 8; ii++) {
        float* yp = g_y + (size_t)(c * CHUNKS + tr * 8 + ii) * QDIM + (size_t)h * HD + tc * 8;
        *(float4*)yp = make_float4(acc[ii][0], acc[ii][1], acc[ii][2], acc[ii][3]);
        *(float4*)(yp + 4) = make_float4(acc[ii][4], acc[ii][5], acc[ii][6], acc[ii][7]);
    }

#pragma unroll
    for (int i = 0; i < 8; i++)
#pragma unroll
        for (int j = 0; j < 8; j++) acc[i][j] = 0.f;
    {
        const int kkl = tid >> 4;
        const int e0 = (tid & 15) * 8;
        for (int j0 = 0; j0 < 128; j0 += 16) {
            const float w = expf(Glast - sG[j0 + kkl]);
            const float dtv = sDt[j0 + kkl];
            const float* kp2 = kp + (size_t)(j0 + kkl) * KVDIM + e0;
            const float* xp = vp + (size_t)(j0 + kkl) * KVDIM + e0;
            float4 k0v = *(const float4*)kp2;
            float4 k1v = *(const float4*)(kp2 + 4);
            float4 x0 = *(const float4*)xp;
            float4 x1 = *(const float4*)(xp + 4);
            sA[kkl * 128 + e0 + 0] = k0v.x * w;
            sA[kkl * 128 + e0 + 1] = k0v.y * w;
            sA[kkl * 128 + e0 + 2] = k0v.z * w;
            sA[kkl * 128 + e0 + 3] = k0v.w * w;
            sA[kkl * 128 + e0 + 4] = k1v.x * w;
            sA[kkl * 128 + e0 + 5] = k1v.y * w;
            sA[kkl * 128 + e0 + 6] = k1v.z * w;
            sA[kkl * 128 + e0 + 7] = k1v.w * w;
            sB[kkl * 128 + e0 + 0] = x0.x * dtv;
            sB[kkl * 128 + e0 + 1] = x0.y * dtv;
            sB[kkl * 128 + e0 + 2] = x0.z * dtv;
            sB[kkl * 128 + e0 + 3] = x0.w * dtv;
            sB[kkl * 128 + e0 + 4] = x1.x * dtv;
            sB[kkl * 128 + e0 + 5] = x1.y * dtv;
            sB[kkl * 128 + e0 + 6] = x1.z * dtv;
            sB[kkl * 128 + e0 + 7] = x1.w * dtv;
            __syncthreads();
#pragma unroll
            for (int kk = 0; kk < 16; kk++) {
                float av[8], bv[8];
#pragma unroll
                for (int i = 0; i < 8; i++) av[i] = sA[kk * 128 + tr * 8 + i];
#pragma unroll
                for (int j = 0; j < 8; j++) bv[j] = sB[kk * 128 + tc * 8 + j];
#pragma unroll
                for (int i = 0; i < 8; i++)
#pragma unroll
                    for (int j = 0; j < 8; j++) acc[i][j] += av[i] * bv[j];
            }
            __syncthreads();
        }
    }
    float* csp = g_cs + (size_t)(c * NH + h) * HD * HD;
#pragma unroll
    for (int ii = 0; ii < 8; ii++) {
        float* cp = csp + (size_t)(tr * 8 + ii) * HD + tc * 8;
        *(float4*)cp = make_float4(acc[ii][0], acc[ii][1], acc[ii][2], acc[ii][3]);
        *(float4*)(cp + 4) = make_float4(acc[ii][4], acc[ii][5], acc[ii][6], acc[ii][7]);
    }
}

// ---------------- sequential chunk recurrence ----------------
__global__ void recur_kernel() {
    const int idx = blockIdx.x * blockDim.x + threadIdx.x;
    if (idx >= NH * HD * HD) return;
    const int h = idx / (HD * HD);
    const int de = idx % (HD * HD);
    float state = 0.f;
#pragma unroll 1
    for (int c = 0; c < NC; c++) {
        const size_t off = (size_t)(c * NH + h) * HD * HD + de;
        g_prev[off] = state;
        state = state * g_cdec[c * NH + h] + g_cs[off];
    }
}

// ---------------- inter-chunk + combine + RMSNorm + SiLU gate ----------------
__global__ void inter_kernel(const float* __restrict__ gnorm) {
    extern __shared__ float smem[];
    float* sY = smem;               // 128*129
    float* sA = sY + 128 * 129;     // 16*128
    float* sB = sA + 16 * 128;      // 16*128
    __shared__ float sG[128];
    __shared__ float sScale[128];
    __shared__ float sGn[128];

    const int c = blockIdx.x, h = blockIdx.y;
    const int tid = threadIdx.x;
    const int tr = tid >> 4, tc = tid & 15;
    const float* qp = g_q + (size_t)(c * CHUNKS) * QDIM + (size_t)h * HD;
    const float* pp = g_prev + (size_t)(c * NH + h) * HD * HD;

    if (tid < 128) {
        sG[tid] = g_G[(c * CHUNKS + tid) * NH + h];
        sGn[tid] = gnorm[tid];
    }
    __syncthreads();

    float acc[8][8];
#pragma unroll
    for (int i = 0; i < 8; i++)
#pragma unroll
        for (int j = 0; j < 8; j++) acc[i][j] = 0.f;

    const int rowA = tid >> 1;
    const int kk0 = (tid & 1) * 8;
    const int kkl = tid >> 4;
    const int e0 = (tid & 15) * 8;
    for (int d0 = 0; d0 < HD; d0 += 16) {
        const float eg = expf(sG[rowA]);
        const float* ap = qp + (size_t)rowA * QDIM + d0 + kk0;
        float4 a0 = *(const float4*)ap;
        float4 a1 = *(const float4*)(ap + 4);
        sA[(kk0 + 0) * 128 + rowA] = a0.x * eg;
        sA[(kk0 + 1) * 128 + rowA] = a0.y * eg;
        sA[(kk0 + 2) * 128 + rowA] = a0.z * eg;
        sA[(kk0 + 3) * 128 + rowA] = a0.w * eg;
        sA[(kk0 + 4) * 128 + rowA] = a1.x * eg;
        sA[(kk0 + 5) * 128 + rowA] = a1.y * eg;
        sA[(kk0 + 6) * 128 + rowA] = a1.z * eg;
        sA[(kk0 + 7) * 128 + rowA] = a1.w * eg;
        const float* bp = pp + (size_t)(d0 + kkl) * HD + e0;
        float4 b0 = *(const float4*)bp;
        float4 b1 = *(const float4*)(bp + 4);
        sB[kkl * 128 + e0 + 0] = b0.x;
        sB[kkl * 128 + e0 + 1] = b0.y;
        sB[kkl * 128 + e0 + 2] = b0.z;
        sB[kkl * 128 + e0 + 3] = b0.w;
        sB[kkl * 128 + e0 + 4] = b1.x;
        sB[kkl * 128 + e0 + 5] = b1.y;
        sB[kkl * 128 + e0 + 6] = b1.z;
        sB[kkl * 128 + e0 + 7] = b1.w;
        __syncthreads();
#pragma unroll
        for (int kk = 0; kk < 16; kk++) {
            float av[8], bv[8];
#pragma unroll
            for (int i = 0; i < 8; i++) av[i] = sA[kk * 128 + tr * 8 + i];
#pragma unroll
            for (int j = 0; j < 8; j++) bv[j] = sB[kk * 128 + tc * 8 + j];
#pragma unroll
            for (int i = 0; i < 8; i++)
#pragma unroll
                for (int j = 0; j < 8; j++) acc[i][j] += av[i] * bv[j];
        }
        __syncthreads();
    }

#pragma unroll
    for (int ii = 0; ii < 8; ii++) {
        const int i = tr * 8 + ii;
        const float* yin = g_y + (size_t)(c * CHUNKS + i) * QDIM + (size_t)h * HD + tc * 8;
#pragma unroll
        for (int jj = 0; jj < 8; jj++) {
            sY[i * 129 + tc * 8 + jj] = acc[ii][jj] + yin[jj];
        }
    }
    __syncthreads();

    if (tid < 128) {
        float s = 0.f;
#pragma unroll 4
        for (int e = 0; e < 128; e++) {
            float t = sY[tid * 129 + e];
            s += t * t;
        }
        sScale[tid] = rsqrtf(s * (1.0f / 128.0f) + 1e-5f);
    }
    __syncthreads();

    for (int idx = tid; idx < 128 * 128; idx += 256) {
        const int i = idx >> 7, e = idx & 127;
        const size_t off = (size_t)(c * CHUNKS + i) * QDIM + (size_t)h * HD + e;
        const float gv = g_gate[off];
        const float sig = 1.f / (1.f + expf(-gv));
        g_y[off] = sY[i * 129 + e] * sScale[i] * sGn[e] * gv * sig;
    }
}

// ---------------- launch ----------------
extern "C" void kernel_launch(void* const* d_in, const int* in_sizes, int n_in,
                              void* d_out, int out_size) {
    const float* hs      = (const float*)d_in[0];
    const float* Wq      = (const float*)d_in[1];
    const float* Wk      = (const float*)d_in[2];
    const float* Wv      = (const float*)d_in[3];
    const float* Wo      = (const float*)d_in[4];
    const float* Wg      = (const float*)d_in[5];
    const float* Win     = (const float*)d_in[6];
    const float* dt_bias = (const float*)d_in[7];
    const float* A_log   = (const float*)d_in[8];
    const float* gnorm   = (const float*)d_in[9];
    float* out = (float*)d_out;

    float *q, *k, *v, *gate, *y;
    cudaGetSymbolAddress((void**)&q, g_q);
    cudaGetSymbolAddress((void**)&k, g_k);
    cudaGetSymbolAddress((void**)&v, g_v);
    cudaGetSymbolAddress((void**)&gate, g_gate);
    cudaGetSymbolAddress((void**)&y, g_y);

    const int SMEM_BIG = (128 * 129 + 2 * 16 * 128) * (int)sizeof(float);
    cudaFuncSetAttribute(intra_kernel, cudaFuncAttributeMaxDynamicSharedMemorySize, SMEM_BIG);
    cudaFuncSetAttribute(inter_kernel, cudaFuncAttributeMaxDynamicSharedMemorySize, SMEM_BIG);
    const int SMEM_GEMM = 16384 * (int)sizeof(unsigned);  // 64KB
    cudaFuncSetAttribute(gemm_bf16x3, cudaFuncAttributeMaxDynamicSharedMemorySize, SMEM_GEMM);

    // projections (tensor core, bf16x3 compensated)
    gemm_bf16x3<<<dim3(QDIM / 128, LSEQ / 128), 256, SMEM_GEMM>>>(hs, Wq, q, LSEQ, QDIM, HIDDEN);
    gemm_bf16x3<<<dim3(KVDIM / 128, LSEQ / 128), 256, SMEM_GEMM>>>(hs, Wk, k, LSEQ, KVDIM, HIDDEN);
    gemm_bf16x3<<<dim3(KVDIM / 128, LSEQ / 128), 256, SMEM_GEMM>>>(hs, Wv, v, LSEQ, KVDIM, HIDDEN);
    gemm_bf16x3<<<dim3(QDIM / 128, LSEQ / 128), 256, SMEM_GEMM>>>(hs, Wg, gate, LSEQ, QDIM, HIDDEN);
    dt_kernel<<<LSEQ, 256>>>(hs, Win, dt_bias);
    scan_kernel<<<NC * NH, 32>>>(A_log);

    // rope
    {
        long tq = (long)LSEQ * NH * 64;
        rope_kernel<<<(unsigned)((tq + 255) / 256), 256>>>(q, NH);
        long tk = (long)LSEQ * NKV * 64;
        rope_kernel<<<(unsigned)((tk + 255) / 256), 256>>>(k, NKV);
    }

    // attention
    intra_kernel<<<dim3(NC, NH), 256, SMEM_BIG>>>();
    recur_kernel<<<(NH * HD * HD + 1023) / 1024, 1024>>>();
    inter_kernel<<<dim3(NC, NH), 256, SMEM_BIG>>>(gnorm);

    // output projection
    gemm_bf16x3<<<dim3(HIDDEN / 128, LSEQ / 128), 256, SMEM_GEMM>>>(y, Wo, out, LSEQ, HIDDEN, QDIM);
}